// round 12
// baseline (speedup 1.0000x reference)
#include <cuda_runtime.h>
#include <math.h>

#define BB 8
#define PP 4096
#define CC 91
#define CM1 90
#define FD 1024
#define DETS 100
#define ROWCAP 512
#define CANDCAP 1024
#define BBOX_CLIP 4.135166556742356f
#define IMGF 800.0f
#define RT 32                       // rows per block in rowmax_k
#define STR 100                     // padded smem row stride (floats)

__device__ unsigned int g_rowmax[BB * PP];
__device__ int g_keptp[BB * DETS];

// ---------------------------------------------------------------------------
// FMA-pipe exp: e^v = 2^(v*log2e), magic-number round-to-nearest, degree-6
// Taylor for 2^f on [-0.5,0.5] (rel err ~1.2e-7). No MUFU. Clamp handles the
// -1e30 padding (maps to ~1e-38, vanishes in the sum).
// ---------------------------------------------------------------------------
__device__ __forceinline__ float fexp(float v) {
    v = fmaxf(v, -80.0f);
    float t = v * 1.4426950408889634f;
    float z = t + 12582912.0f;                   // 1.5*2^23: round-to-nearest
    int e = __float_as_int(z) - 0x4B400000;      // integer part
    float r = z - 12582912.0f;
    float f = t - r;                             // f in [-0.5, 0.5]
    float p = 1.5403530393381609e-4f;
    p = fmaf(p, f, 1.3333558146428443e-3f);
    p = fmaf(p, f, 9.6181291076284772e-3f);
    p = fmaf(p, f, 5.5504108664821580e-2f);
    p = fmaf(p, f, 2.4022650695910072e-1f);
    p = fmaf(p, f, 6.9314718055994531e-1f);
    p = fmaf(p, f, 1.0f);
    return p * __int_as_float((e + 127) << 23);  // * 2^e
}

// ---------------------------------------------------------------------------
// K1: 8 threads/row, 32 rows/block, 256 thr, grid=1024. Stage 728 float4 ->
// smem padded to stride 100 (cols 91..95 = -1e30), 3 conflict-free LDS.128
// per thread, 12 polynomial exps on the FMA pipe (zero MUFU in hot path),
// fmax tree, 3-level shuffle. score = fexp(maxlogit_1_90)/sum(fexp(all)).
// ---------------------------------------------------------------------------
__global__ void __launch_bounds__(256) rowmax_k(const float* __restrict__ logits) {
    __shared__ float s[RT * STR];              // 12800 bytes
    int tid = threadIdx.x;
    const float4* src = (const float4*)(logits + (size_t)blockIdx.x * RT * CC); // 728 f4
    #pragma unroll
    for (int k = 0; k < 3; k++) {
        int i = tid + k * 256;
        if (i < 728) {
            float4 v = src[i];
            int e = 4 * i;
            int r0 = e / 91,      c0 = e - 91 * r0;
            int r1 = (e + 1) / 91, c1 = (e + 1) - 91 * r1;
            int r2 = (e + 2) / 91, c2 = (e + 2) - 91 * r2;
            int r3 = (e + 3) / 91, c3 = (e + 3) - 91 * r3;
            s[r0 * STR + c0] = v.x;
            s[r1 * STR + c1] = v.y;
            s[r2 * STR + c2] = v.z;
            s[r3 * STR + c3] = v.w;
        }
    }
    if (tid < 160) {                           // pad cols 91..95 of 32 rows
        int r = tid / 5, c = 91 + tid % 5;
        s[r * STR + c] = -1e30f;
    }
    __syncthreads();

    int row = tid >> 3, sub = tid & 7;
    const float4* r4 = (const float4*)(s + row * STR + sub * 12);
    float4 A = r4[0], B = r4[1], C = r4[2];

    float sum = ((fexp(A.x) + fexp(A.y)) + (fexp(A.z) + fexp(A.w)))
              + ((fexp(B.x) + fexp(B.y)) + (fexp(B.z) + fexp(B.w)))
              + ((fexp(C.x) + fexp(C.y)) + (fexp(C.z) + fexp(C.w)));

    float ax = (sub == 0) ? -1e30f : A.x;      // class 0 excluded from max
    float m = fmaxf(fmaxf(fmaxf(ax, A.y), fmaxf(A.z, A.w)),
                    fmaxf(fmaxf(fmaxf(B.x, B.y), fmaxf(B.z, B.w)),
                          fmaxf(fmaxf(C.x, C.y), fmaxf(C.z, C.w))));

    #pragma unroll
    for (int o = 1; o < 8; o <<= 1) {
        sum += __shfl_xor_sync(0xffffffffu, sum, o);
        m = fmaxf(m, __shfl_xor_sync(0xffffffffu, m, o));
    }

    if (sub == 0)
        g_rowmax[blockIdx.x * RT + row] = __float_as_uint(fexp(m) / sum);
}

// ---------------------------------------------------------------------------
// Warp-parallel descending threshold search over 256-bin histogram (tid<32).
// ---------------------------------------------------------------------------
__device__ __forceinline__ void find_thresh(const int* h, int need, int* s_b, int* s_cum) {
    int L = threadIdx.x;
    int hi = 255 - 8 * L;
    int hb[8], cs = 0;
    #pragma unroll
    for (int j = 0; j < 8; j++) { hb[j] = h[hi - j]; cs += hb[j]; }
    int pref = cs;
    #pragma unroll
    for (int o = 1; o < 32; o <<= 1) {
        int t = __shfl_up_sync(0xffffffffu, pref, o);
        if (L >= o) pref += t;
    }
    int above = pref - cs;
    if (above < need && need <= pref) {
        int cum = above;
        #pragma unroll
        for (int j = 0; j < 8; j++) {
            if (cum + hb[j] >= need) { *s_b = hi - j; *s_cum = cum; break; }
            cum += hb[j];
        }
    }
}

// ---------------------------------------------------------------------------
// K2: one block (1024 threads) per image. 2-level radix threshold on approx
// rowmaxes (margins cover fexp error), compact rows, exact re-softmax,
// exact top-100 by rank-counting, decode + clip + scale boxes. Gather is a
// SEPARATE wide kernel (R10 lesson: 400KB/SM through one LSU is the wall).
// ---------------------------------------------------------------------------
__global__ void __launch_bounds__(1024, 1) select_k(const float* __restrict__ logits,
                                                    const float* __restrict__ reg,
                                                    const float* __restrict__ props,
                                                    float* __restrict__ out) {
    __shared__ unsigned vals[PP];
    __shared__ int h[256];
    __shared__ int rowbuf[ROWCAP];
    __shared__ unsigned long long cand[CANDCAP];
    __shared__ int s_nrows, s_ncand, s_b1, s_cumAbove, s_fb, s_fcum;

    int img = blockIdx.x;
    int tid = threadIdx.x;
    int lane = tid & 31;

    for (int i = tid; i < PP; i += 1024) vals[i] = g_rowmax[img * PP + i];
    if (tid < 256) h[tid] = 0;
    if (tid == 0) { s_nrows = 0; s_ncand = 0; }
    __syncthreads();
    for (int i = tid; i < PP; i += 1024) {
        int bin = vals[i] >> 22;
        unsigned peers = __match_any_sync(0xffffffffu, bin);
        if (lane == __ffs(peers) - 1) atomicAdd(&h[bin], __popc(peers));
    }
    __syncthreads();
    if (tid < 32) find_thresh(h, DETS, &s_b1, &s_cumAbove);
    __syncthreads();
    int b1 = s_b1;

    if (tid < 256) h[tid] = 0;
    __syncthreads();
    for (int i = tid; i < PP; i += 1024) {
        unsigned v = vals[i];
        bool pred = ((int)(v >> 22) == b1);
        unsigned active = __ballot_sync(0xffffffffu, pred);
        if (pred) {
            int bin = (v >> 14) & 0xFF;
            unsigned peers = __match_any_sync(active, bin);
            if (lane == __ffs(peers) - 1) atomicAdd(&h[bin], __popc(peers));
        }
    }
    __syncthreads();
    if (tid < 32) find_thresh(h, DETS - s_cumAbove, &s_fb, &s_fcum);
    __syncthreads();
    unsigned T = ((unsigned)b1 << 8) | (unsigned)s_fb;
    unsigned Tc = (T >= 2) ? T - 2 : 0;   // row compaction threshold (approx margin)
    unsigned Te = (T >= 1) ? T - 1 : 0;   // candidate emission threshold

    for (int i = tid; i < PP; i += 1024) {
        bool keep = (vals[i] >> 14) >= Tc;
        unsigned b = __ballot_sync(0xffffffffu, keep);
        int cnt = __popc(b);
        if (cnt) {
            int basepos = 0;
            if (lane == 0) basepos = atomicAdd(&s_nrows, cnt);
            basepos = __shfl_sync(0xffffffffu, basepos, 0);
            if (keep) {
                int pos = basepos + __popc(b & ((1u << lane) - 1));
                if (pos < ROWCAP) rowbuf[pos] = i;
            }
        }
    }
    __syncthreads();
    int nrows = min(s_nrows, ROWCAP);

    int warp = tid >> 5;
    for (int r = warp; r < nrows; r += 32) {
        int p = rowbuf[r];
        const float* l = logits + (size_t)(img * PP + p) * CC;
        float v0 = l[lane];
        float v1 = l[lane + 32];
        float v2 = (lane < 27) ? l[lane + 64] : -1e30f;
        float m = fmaxf(v0, fmaxf(v1, v2));
        #pragma unroll
        for (int o = 16; o; o >>= 1) m = fmaxf(m, __shfl_xor_sync(0xffffffffu, m, o));
        float e0 = expf(v0 - m);
        float e1 = expf(v1 - m);
        float e2 = (lane < 27) ? expf(v2 - m) : 0.0f;
        float s = e0 + e1 + e2;
        #pragma unroll
        for (int o = 16; o; o >>= 1) s += __shfl_xor_sync(0xffffffffu, s, o);

        unsigned base = (unsigned)p * CM1;
        if (lane > 0) {
            unsigned b = __float_as_uint(e0 / s);
            if ((b >> 14) >= Te) {
                int pos = atomicAdd(&s_ncand, 1);
                if (pos < CANDCAP)
                    cand[pos] = (((unsigned long long)b) << 32) | (unsigned)(~(base + lane - 1));
            }
        }
        {
            unsigned b = __float_as_uint(e1 / s);
            if ((b >> 14) >= Te) {
                int pos = atomicAdd(&s_ncand, 1);
                if (pos < CANDCAP)
                    cand[pos] = (((unsigned long long)b) << 32) | (unsigned)(~(base + lane + 31));
            }
        }
        if (lane < 27) {
            unsigned b = __float_as_uint(e2 / s);
            if ((b >> 14) >= Te) {
                int pos = atomicAdd(&s_ncand, 1);
                if (pos < CANDCAP)
                    cand[pos] = (((unsigned long long)b) << 32) | (unsigned)(~(base + lane + 63));
            }
        }
    }
    __syncthreads();

    int nc = min(s_ncand, CANDCAP);
    for (int i = tid; i < nc; i += 1024) {
        unsigned long long my = cand[i];
        int rank = 0;
        for (int j = 0; j < nc; j++) rank += (cand[j] > my);
        if (rank < DETS) {
            unsigned idxl = ~(unsigned)(my & 0xFFFFFFFFull);
            int p = idxl / CM1;
            int c = idxl - p * CM1 + 1;

            const float* pr = props + ((size_t)img * PP + p) * 4;
            float x1 = pr[0], y1 = pr[1], x2 = pr[2], y2 = pr[3];
            float w = x2 - x1, hh = y2 - y1;
            float cx = x1 + 0.5f * w, cy = y1 + 0.5f * hh;

            const float* rg = reg + ((size_t)img * PP + p) * (4 * CC) + 4 * c;
            float dx = rg[0] / 10.0f;
            float dy = rg[1] / 10.0f;
            float dw = fminf(rg[2] / 5.0f, BBOX_CLIP);
            float dh = fminf(rg[3] / 5.0f, BBOX_CLIP);

            float pcx = dx * w + cx, pcy = dy * hh + cy;
            float pw = expf(dw) * w, ph = expf(dh) * hh;

            float bx1 = fminf(fmaxf(pcx - 0.5f * pw, 0.0f), IMGF);
            float by1 = fminf(fmaxf(pcy - 0.5f * ph, 0.0f), IMGF);
            float bx2 = fminf(fmaxf(pcx + 0.5f * pw, 0.0f), IMGF);
            float by2 = fminf(fmaxf(pcy + 0.5f * ph, 0.0f), IMGF);

            float* ob = out + ((size_t)img * DETS + rank) * 4;
            ob[0] = bx1 / IMGF;
            ob[1] = by1 / IMGF;
            ob[2] = bx2 / IMGF;
            ob[3] = by2 / IMGF;
            g_keptp[img * DETS + rank] = p;
        }
    }
}

// ---------------------------------------------------------------------------
// K3: feature gather, WIDE (one block per detection), float4 vectorized.
// ---------------------------------------------------------------------------
__global__ void gather_k(const float* __restrict__ feats, float* __restrict__ out) {
    int img = blockIdx.x / DETS;
    int p = g_keptp[blockIdx.x];
    const float4* src = (const float4*)(feats + ((size_t)img * PP + p) * FD);
    float4* dst = (float4*)(out + BB * DETS * 4 + (size_t)blockIdx.x * FD);
    dst[threadIdx.x] = src[threadIdx.x];
}

extern "C" void kernel_launch(void* const* d_in, const int* in_sizes, int n_in,
                              void* d_out, int out_size) {
    const float* logits = (const float*)d_in[0];
    const float* reg    = (const float*)d_in[1];
    const float* props  = (const float*)d_in[2];
    const float* feats  = (const float*)d_in[3];
    float* out = (float*)d_out;

    rowmax_k<<<BB * PP / RT, 256>>>(logits);
    select_k<<<BB, 1024>>>(logits, reg, props, out);
    gather_k<<<BB * DETS, 256>>>(feats, out);
}

// round 15
// speedup vs baseline: 1.1390x; 1.1390x over previous
#include <cuda_runtime.h>
#include <math.h>

#define BB 8
#define PP 4096
#define CC 91
#define CM1 90
#define FD 1024
#define DETS 100
#define ROWCAP 512
#define CANDCAP 1024
#define BBOX_CLIP 4.135166556742356f
#define IMGF 800.0f
#define RT 64                        // rows per rowmax block
#define STR 100                      // padded smem row stride (floats)

#define NB_RM 512                    // rowmax blocks (64 per image)
#define RMB_PER_IMG 64
#define NB_SEL 8
#define GA_PER_IMG 50                // gather blocks per image (2 dets each)
#define NB_GA (BB * GA_PER_IMG)
#define NBLOCKS (NB_RM + NB_SEL + NB_GA)

__device__ unsigned int g_rowmax[BB * PP];
__device__ int g_keptp[BB * DETS];
__device__ int g_rm_cnt[BB];         // rowmax-blocks-done counter per image
__device__ int g_sel_done[BB];       // select-done flag per image
__device__ int g_ga_arr[BB];         // gather-blocks-arrived counter per image

// ---------------------------------------------------------------------------
// Warp-parallel descending threshold search over 256-bin histogram (tid<32).
// ---------------------------------------------------------------------------
__device__ __forceinline__ void find_thresh(const int* h, int need, int* s_b, int* s_cum) {
    int L = threadIdx.x;
    int hi = 255 - 8 * L;
    int hb[8], cs = 0;
    #pragma unroll
    for (int j = 0; j < 8; j++) { hb[j] = h[hi - j]; cs += hb[j]; }
    int pref = cs;
    #pragma unroll
    for (int o = 1; o < 32; o <<= 1) {
        int t = __shfl_up_sync(0xffffffffu, pref, o);
        if (L >= o) pref += t;
    }
    int above = pref - cs;
    if (above < need && need <= pref) {
        int cum = above;
        #pragma unroll
        for (int j = 0; j < 8; j++) {
            if (cum + hb[j] >= need) { *s_b = hi - j; *s_cum = cum; break; }
            cum += hb[j];
        }
    }
}

// ---------------------------------------------------------------------------
// ONE fused kernel. Device-side flag sync replaces 2 kernel-launch boundaries.
//   blocks [0,512):    rowmax (8 thr/row, vec4 smem staging, __expf)
//   blocks [512,520):  per-image select (spin on g_rm_cnt == 64)
//   blocks [520,920):  gather, 2 dets/block (spin on g_sel_done)
// Flags are reset in-kernel by their consumers so graph replay is clean.
// ---------------------------------------------------------------------------
__global__ void __launch_bounds__(512) fused_k(const float* __restrict__ logits,
                                               const float* __restrict__ reg,
                                               const float* __restrict__ props,
                                               const float* __restrict__ feats,
                                               float* __restrict__ out) {
    __shared__ __align__(16) char smem_raw[27712];
    int bid = blockIdx.x;
    int tid = threadIdx.x;

    if (bid < NB_RM) {
        // ------------------------- rowmax role ---------------------------
        float* s = (float*)smem_raw;               // 64*100 floats = 25600 B
        const float4* src = (const float4*)(logits + (size_t)bid * RT * CC); // 1456 f4
        #pragma unroll
        for (int k = 0; k < 3; k++) {
            int i = tid + k * 512;
            if (i < 1456) {
                float4 v = src[i];
                int e = 4 * i;
                int r0 = e / 91,       c0 = e - 91 * r0;
                int r1 = (e + 1) / 91, c1 = (e + 1) - 91 * r1;
                int r2 = (e + 2) / 91, c2 = (e + 2) - 91 * r2;
                int r3 = (e + 3) / 91, c3 = (e + 3) - 91 * r3;
                s[r0 * STR + c0] = v.x;
                s[r1 * STR + c1] = v.y;
                s[r2 * STR + c2] = v.z;
                s[r3 * STR + c3] = v.w;
            }
        }
        if (tid < 320) {                           // pad cols 91..95 of 64 rows
            int r = tid / 5, c = 91 + tid % 5;
            s[r * STR + c] = -1e30f;
        }
        __syncthreads();

        int row = tid >> 3, sub = tid & 7;
        const float4* r4 = (const float4*)(s + row * STR + sub * 12);
        float4 A = r4[0], B = r4[1], C = r4[2];

        float sum = ((__expf(A.x) + __expf(A.y)) + (__expf(A.z) + __expf(A.w)))
                  + ((__expf(B.x) + __expf(B.y)) + (__expf(B.z) + __expf(B.w)))
                  + ((__expf(C.x) + __expf(C.y)) + (__expf(C.z) + __expf(C.w)));

        float ax = (sub == 0) ? -1e30f : A.x;      // class 0 excluded from max
        float m = fmaxf(fmaxf(fmaxf(ax, A.y), fmaxf(A.z, A.w)),
                        fmaxf(fmaxf(fmaxf(B.x, B.y), fmaxf(B.z, B.w)),
                              fmaxf(fmaxf(C.x, C.y), fmaxf(C.z, C.w))));

        #pragma unroll
        for (int o = 1; o < 8; o <<= 1) {
            sum += __shfl_xor_sync(0xffffffffu, sum, o);
            m = fmaxf(m, __shfl_xor_sync(0xffffffffu, m, o));
        }

        if (sub == 0)
            g_rowmax[bid * RT + row] = __float_as_uint(__expf(m) / sum);

        __syncthreads();
        if (tid == 0) {
            __threadfence();
            atomicAdd(&g_rm_cnt[bid / RMB_PER_IMG], 1);
        }
        return;
    }

    if (bid < NB_RM + NB_SEL) {
        // ------------------------- select role ---------------------------
        unsigned* vals = (unsigned*)smem_raw;                        // 16384 B
        unsigned long long* cand = (unsigned long long*)(smem_raw + 16384); // 8192 B
        int* rowbuf = (int*)(smem_raw + 24576);                      // 2048 B
        int* h = (int*)(smem_raw + 26624);                           // 1024 B
        int* sc = (int*)(smem_raw + 27648);                          // scalars
        // sc[0]=nrows sc[1]=ncand sc[2]=b1 sc[3]=cumAbove sc[4]=fb sc[5]=fcum

        int img = bid - NB_RM;
        int lane = tid & 31;

        if (tid == 0) {
            while (atomicAdd(&g_rm_cnt[img], 0) < RMB_PER_IMG) __nanosleep(64);
            atomicExch(&g_rm_cnt[img], 0);         // consumer reset for replay
        }
        __syncthreads();
        __threadfence();

        for (int i = tid; i < PP; i += 512) vals[i] = g_rowmax[img * PP + i];
        if (tid < 256) h[tid] = 0;
        if (tid == 0) { sc[0] = 0; sc[1] = 0; }
        __syncthreads();
        for (int i = tid; i < PP; i += 512) {
            int bin = vals[i] >> 22;
            unsigned peers = __match_any_sync(0xffffffffu, bin);
            if (lane == __ffs(peers) - 1) atomicAdd(&h[bin], __popc(peers));
        }
        __syncthreads();
        if (tid < 32) find_thresh(h, DETS, &sc[2], &sc[3]);
        __syncthreads();
        int b1 = sc[2];

        if (tid < 256) h[tid] = 0;
        __syncthreads();
        for (int i = tid; i < PP; i += 512) {
            unsigned v = vals[i];
            bool pred = ((int)(v >> 22) == b1);
            unsigned active = __ballot_sync(0xffffffffu, pred);
            if (pred) {
                int bin = (v >> 14) & 0xFF;
                unsigned peers = __match_any_sync(active, bin);
                if (lane == __ffs(peers) - 1) atomicAdd(&h[bin], __popc(peers));
            }
        }
        __syncthreads();
        if (tid < 32) find_thresh(h, DETS - sc[3], &sc[4], &sc[5]);
        __syncthreads();
        unsigned T = ((unsigned)b1 << 8) | (unsigned)sc[4];
        unsigned Tc = (T >= 2) ? T - 2 : 0;
        unsigned Te = (T >= 1) ? T - 1 : 0;

        for (int i = tid; i < PP; i += 512) {
            bool keep = (vals[i] >> 14) >= Tc;
            unsigned b = __ballot_sync(0xffffffffu, keep);
            int cnt = __popc(b);
            if (cnt) {
                int basepos = 0;
                if (lane == 0) basepos = atomicAdd(&sc[0], cnt);
                basepos = __shfl_sync(0xffffffffu, basepos, 0);
                if (keep) {
                    int pos = basepos + __popc(b & ((1u << lane) - 1));
                    if (pos < ROWCAP) rowbuf[pos] = i;
                }
            }
        }
        __syncthreads();
        int nrows = min(sc[0], ROWCAP);

        int warp = tid >> 5;
        for (int r = warp; r < nrows; r += 16) {
            int p = rowbuf[r];
            const float* l = logits + (size_t)(img * PP + p) * CC;
            float v0 = l[lane];
            float v1 = l[lane + 32];
            float v2 = (lane < 27) ? l[lane + 64] : -1e30f;
            float m = fmaxf(v0, fmaxf(v1, v2));
            #pragma unroll
            for (int o = 16; o; o >>= 1) m = fmaxf(m, __shfl_xor_sync(0xffffffffu, m, o));
            float e0 = expf(v0 - m);
            float e1 = expf(v1 - m);
            float e2 = (lane < 27) ? expf(v2 - m) : 0.0f;
            float s = e0 + e1 + e2;
            #pragma unroll
            for (int o = 16; o; o >>= 1) s += __shfl_xor_sync(0xffffffffu, s, o);

            unsigned base = (unsigned)p * CM1;
            if (lane > 0) {
                unsigned b = __float_as_uint(e0 / s);
                if ((b >> 14) >= Te) {
                    int pos = atomicAdd(&sc[1], 1);
                    if (pos < CANDCAP)
                        cand[pos] = (((unsigned long long)b) << 32) | (unsigned)(~(base + lane - 1));
                }
            }
            {
                unsigned b = __float_as_uint(e1 / s);
                if ((b >> 14) >= Te) {
                    int pos = atomicAdd(&sc[1], 1);
                    if (pos < CANDCAP)
                        cand[pos] = (((unsigned long long)b) << 32) | (unsigned)(~(base + lane + 31));
                }
            }
            if (lane < 27) {
                unsigned b = __float_as_uint(e2 / s);
                if ((b >> 14) >= Te) {
                    int pos = atomicAdd(&sc[1], 1);
                    if (pos < CANDCAP)
                        cand[pos] = (((unsigned long long)b) << 32) | (unsigned)(~(base + lane + 63));
                }
            }
        }
        __syncthreads();

        int nc = min(sc[1], CANDCAP);
        for (int i = tid; i < nc; i += 512) {
            unsigned long long my = cand[i];
            int rank = 0;
            for (int j = 0; j < nc; j++) rank += (cand[j] > my);
            if (rank < DETS) {
                unsigned idxl = ~(unsigned)(my & 0xFFFFFFFFull);
                int p = idxl / CM1;
                int c = idxl - p * CM1 + 1;

                const float* pr = props + ((size_t)img * PP + p) * 4;
                float x1 = pr[0], y1 = pr[1], x2 = pr[2], y2 = pr[3];
                float w = x2 - x1, hh = y2 - y1;
                float cx = x1 + 0.5f * w, cy = y1 + 0.5f * hh;

                const float* rg = reg + ((size_t)img * PP + p) * (4 * CC) + 4 * c;
                float dx = rg[0] / 10.0f;
                float dy = rg[1] / 10.0f;
                float dw = fminf(rg[2] / 5.0f, BBOX_CLIP);
                float dh = fminf(rg[3] / 5.0f, BBOX_CLIP);

                float pcx = dx * w + cx, pcy = dy * hh + cy;
                float pw = expf(dw) * w, ph = expf(dh) * hh;

                float bx1 = fminf(fmaxf(pcx - 0.5f * pw, 0.0f), IMGF);
                float by1 = fminf(fmaxf(pcy - 0.5f * ph, 0.0f), IMGF);
                float bx2 = fminf(fmaxf(pcx + 0.5f * pw, 0.0f), IMGF);
                float by2 = fminf(fmaxf(pcy + 0.5f * ph, 0.0f), IMGF);

                float* ob = out + ((size_t)img * DETS + rank) * 4;
                ob[0] = bx1 / IMGF;
                ob[1] = by1 / IMGF;
                ob[2] = bx2 / IMGF;
                ob[3] = by2 / IMGF;
                g_keptp[img * DETS + rank] = p;
            }
        }
        __syncthreads();
        if (tid == 0) {
            __threadfence();
            atomicExch(&g_sel_done[img], 1);
        }
        return;
    }

    // --------------------------- gather role -----------------------------
    {
        int b = bid - (NB_RM + NB_SEL);
        int img = b / GA_PER_IMG;

        if (tid == 0) {
            while (atomicAdd(&g_sel_done[img], 0) == 0) __nanosleep(64);
            // consumer-count reset: last arriving gather block clears flags
            if (atomicAdd(&g_ga_arr[img], 1) == GA_PER_IMG - 1) {
                atomicExch(&g_sel_done[img], 0);
                atomicExch(&g_ga_arr[img], 0);
            }
        }
        __syncthreads();
        __threadfence();

        int d = (b % GA_PER_IMG) * 2 + (tid >> 8);   // 2 detections per block
        int off = tid & 255;
        int p = g_keptp[img * DETS + d];
        const float4* srcf = (const float4*)(feats + ((size_t)img * PP + p) * FD);
        float4* dst = (float4*)(out + BB * DETS * 4 + ((size_t)img * DETS + d) * FD);
        dst[off] = srcf[off];
    }
}

extern "C" void kernel_launch(void* const* d_in, const int* in_sizes, int n_in,
                              void* d_out, int out_size) {
    const float* logits = (const float*)d_in[0];
    const float* reg    = (const float*)d_in[1];
    const float* props  = (const float*)d_in[2];
    const float* feats  = (const float*)d_in[3];
    float* out = (float*)d_out;

    fused_k<<<NBLOCKS, 512>>>(logits, reg, props, feats, out);
}

// round 17
// speedup vs baseline: 1.4684x; 1.2892x over previous
#include <cuda_runtime.h>
#include <math.h>

#define BB 8
#define PP 4096
#define CC 91
#define CM1 90
#define FD 1024
#define DETS 100
#define ROWCAP 512
#define CANDCAP 1024
#define BBOX_CLIP 4.135166556742356f
#define IMGF 800.0f
#define RT 32                       // rows per block in rowmax_k
#define STR 100                     // padded smem row stride (floats)

__device__ unsigned int g_rowmax[BB * PP];
__device__ int g_keptp[BB * DETS];

// ---------------------------------------------------------------------------
// K1 (best measured variant, 6.88us): 8 thr/row, 32 rows/block, 256 thr,
// grid=1024. Vec4 stage -> stride-100 smem, 3 conflict-free LDS.128,
// 12 MUFU exp, fmax tree, 3-level shuffle. Fires PDL trigger at the end.
// ---------------------------------------------------------------------------
__global__ void __launch_bounds__(256) rowmax_k(const float* __restrict__ logits) {
    __shared__ float s[RT * STR];              // 12800 bytes
    int tid = threadIdx.x;
    const float4* src = (const float4*)(logits + (size_t)blockIdx.x * RT * CC); // 728 f4
    #pragma unroll
    for (int k = 0; k < 3; k++) {
        int i = tid + k * 256;
        if (i < 728) {
            float4 v = src[i];
            int e = 4 * i;
            int r0 = e / 91,       c0 = e - 91 * r0;
            int r1 = (e + 1) / 91, c1 = (e + 1) - 91 * r1;
            int r2 = (e + 2) / 91, c2 = (e + 2) - 91 * r2;
            int r3 = (e + 3) / 91, c3 = (e + 3) - 91 * r3;
            s[r0 * STR + c0] = v.x;
            s[r1 * STR + c1] = v.y;
            s[r2 * STR + c2] = v.z;
            s[r3 * STR + c3] = v.w;
        }
    }
    if (tid < 160) {                           // pad cols 91..95 of 32 rows
        int r = tid / 5, c = 91 + tid % 5;
        s[r * STR + c] = -1e30f;
    }
    __syncthreads();

    int row = tid >> 3, sub = tid & 7;
    const float4* r4 = (const float4*)(s + row * STR + sub * 12);
    float4 A = r4[0], B = r4[1], C = r4[2];

    float sum = ((__expf(A.x) + __expf(A.y)) + (__expf(A.z) + __expf(A.w)))
              + ((__expf(B.x) + __expf(B.y)) + (__expf(B.z) + __expf(B.w)))
              + ((__expf(C.x) + __expf(C.y)) + (__expf(C.z) + __expf(C.w)));

    float ax = (sub == 0) ? -1e30f : A.x;      // class 0 excluded from max
    float m = fmaxf(fmaxf(fmaxf(ax, A.y), fmaxf(A.z, A.w)),
                    fmaxf(fmaxf(fmaxf(B.x, B.y), fmaxf(B.z, B.w)),
                          fmaxf(fmaxf(C.x, C.y), fmaxf(C.z, C.w))));

    #pragma unroll
    for (int o = 1; o < 8; o <<= 1) {
        sum += __shfl_xor_sync(0xffffffffu, sum, o);
        m = fmaxf(m, __shfl_xor_sync(0xffffffffu, m, o));
    }

    if (sub == 0)
        g_rowmax[blockIdx.x * RT + row] = __float_as_uint(__expf(m) / sum);

#if defined(__CUDA_ARCH__) && __CUDA_ARCH__ >= 900
    cudaTriggerProgrammaticLaunchCompletion();
#endif
}

// ---------------------------------------------------------------------------
// Warp-parallel descending threshold search over 256-bin histogram (tid<32).
// ---------------------------------------------------------------------------
__device__ __forceinline__ void find_thresh(const int* h, int need, int* s_b, int* s_cum) {
    int L = threadIdx.x;
    int hi = 255 - 8 * L;
    int hb[8], cs = 0;
    #pragma unroll
    for (int j = 0; j < 8; j++) { hb[j] = h[hi - j]; cs += hb[j]; }
    int pref = cs;
    #pragma unroll
    for (int o = 1; o < 32; o <<= 1) {
        int t = __shfl_up_sync(0xffffffffu, pref, o);
        if (L >= o) pref += t;
    }
    int above = pref - cs;
    if (above < need && need <= pref) {
        int cum = above;
        #pragma unroll
        for (int j = 0; j < 8; j++) {
            if (cum + hb[j] >= need) { *s_b = hi - j; *s_cum = cum; break; }
            cum += hb[j];
        }
    }
}

// ---------------------------------------------------------------------------
// K2: one block (1024 threads) per image. PDL-synced on rowmax. 2-level radix
// threshold on approx rowmaxes (margins cover __expf error), compact rows,
// exact re-softmax, exact top-100 by rank-counting, decode+clip+scale boxes.
// ---------------------------------------------------------------------------
__global__ void __launch_bounds__(1024, 1) select_k(const float* __restrict__ logits,
                                                    const float* __restrict__ reg,
                                                    const float* __restrict__ props,
                                                    float* __restrict__ out) {
    __shared__ unsigned vals[PP];
    __shared__ int h[256];
    __shared__ int rowbuf[ROWCAP];
    __shared__ unsigned long long cand[CANDCAP];
    __shared__ int s_nrows, s_ncand, s_b1, s_cumAbove, s_fb, s_fcum;

#if defined(__CUDA_ARCH__) && __CUDA_ARCH__ >= 900
    cudaGridDependencySynchronize();           // rowmax results now visible
#endif

    int img = blockIdx.x;
    int tid = threadIdx.x;
    int lane = tid & 31;

    for (int i = tid; i < PP; i += 1024) vals[i] = g_rowmax[img * PP + i];
    if (tid < 256) h[tid] = 0;
    if (tid == 0) { s_nrows = 0; s_ncand = 0; }
    __syncthreads();
    for (int i = tid; i < PP; i += 1024) {
        int bin = vals[i] >> 22;
        unsigned peers = __match_any_sync(0xffffffffu, bin);
        if (lane == __ffs(peers) - 1) atomicAdd(&h[bin], __popc(peers));
    }
    __syncthreads();
    if (tid < 32) find_thresh(h, DETS, &s_b1, &s_cumAbove);
    __syncthreads();
    int b1 = s_b1;

    if (tid < 256) h[tid] = 0;
    __syncthreads();
    for (int i = tid; i < PP; i += 1024) {
        unsigned v = vals[i];
        bool pred = ((int)(v >> 22) == b1);
        unsigned active = __ballot_sync(0xffffffffu, pred);
        if (pred) {
            int bin = (v >> 14) & 0xFF;
            unsigned peers = __match_any_sync(active, bin);
            if (lane == __ffs(peers) - 1) atomicAdd(&h[bin], __popc(peers));
        }
    }
    __syncthreads();
    if (tid < 32) find_thresh(h, DETS - s_cumAbove, &s_fb, &s_fcum);
    __syncthreads();
    unsigned T = ((unsigned)b1 << 8) | (unsigned)s_fb;
    unsigned Tc = (T >= 2) ? T - 2 : 0;   // row compaction threshold (approx margin)
    unsigned Te = (T >= 1) ? T - 1 : 0;   // candidate emission threshold

    for (int i = tid; i < PP; i += 1024) {
        bool keep = (vals[i] >> 14) >= Tc;
        unsigned b = __ballot_sync(0xffffffffu, keep);
        int cnt = __popc(b);
        if (cnt) {
            int basepos = 0;
            if (lane == 0) basepos = atomicAdd(&s_nrows, cnt);
            basepos = __shfl_sync(0xffffffffu, basepos, 0);
            if (keep) {
                int pos = basepos + __popc(b & ((1u << lane) - 1));
                if (pos < ROWCAP) rowbuf[pos] = i;
            }
        }
    }
    __syncthreads();
    int nrows = min(s_nrows, ROWCAP);

    int warp = tid >> 5;
    for (int r = warp; r < nrows; r += 32) {
        int p = rowbuf[r];
        const float* l = logits + (size_t)(img * PP + p) * CC;
        float v0 = l[lane];
        float v1 = l[lane + 32];
        float v2 = (lane < 27) ? l[lane + 64] : -1e30f;
        float m = fmaxf(v0, fmaxf(v1, v2));
        #pragma unroll
        for (int o = 16; o; o >>= 1) m = fmaxf(m, __shfl_xor_sync(0xffffffffu, m, o));
        float e0 = expf(v0 - m);
        float e1 = expf(v1 - m);
        float e2 = (lane < 27) ? expf(v2 - m) : 0.0f;
        float s = e0 + e1 + e2;
        #pragma unroll
        for (int o = 16; o; o >>= 1) s += __shfl_xor_sync(0xffffffffu, s, o);

        unsigned base = (unsigned)p * CM1;
        if (lane > 0) {
            unsigned b = __float_as_uint(e0 / s);
            if ((b >> 14) >= Te) {
                int pos = atomicAdd(&s_ncand, 1);
                if (pos < CANDCAP)
                    cand[pos] = (((unsigned long long)b) << 32) | (unsigned)(~(base + lane - 1));
            }
        }
        {
            unsigned b = __float_as_uint(e1 / s);
            if ((b >> 14) >= Te) {
                int pos = atomicAdd(&s_ncand, 1);
                if (pos < CANDCAP)
                    cand[pos] = (((unsigned long long)b) << 32) | (unsigned)(~(base + lane + 31));
            }
        }
        if (lane < 27) {
            unsigned b = __float_as_uint(e2 / s);
            if ((b >> 14) >= Te) {
                int pos = atomicAdd(&s_ncand, 1);
                if (pos < CANDCAP)
                    cand[pos] = (((unsigned long long)b) << 32) | (unsigned)(~(base + lane + 63));
            }
        }
    }
    __syncthreads();

    int nc = min(s_ncand, CANDCAP);
    for (int i = tid; i < nc; i += 1024) {
        unsigned long long my = cand[i];
        int rank = 0;
        for (int j = 0; j < nc; j++) rank += (cand[j] > my);
        if (rank < DETS) {
            unsigned idxl = ~(unsigned)(my & 0xFFFFFFFFull);
            int p = idxl / CM1;
            int c = idxl - p * CM1 + 1;

            const float* pr = props + ((size_t)img * PP + p) * 4;
            float x1 = pr[0], y1 = pr[1], x2 = pr[2], y2 = pr[3];
            float w = x2 - x1, hh = y2 - y1;
            float cx = x1 + 0.5f * w, cy = y1 + 0.5f * hh;

            const float* rg = reg + ((size_t)img * PP + p) * (4 * CC) + 4 * c;
            float dx = rg[0] / 10.0f;
            float dy = rg[1] / 10.0f;
            float dw = fminf(rg[2] / 5.0f, BBOX_CLIP);
            float dh = fminf(rg[3] / 5.0f, BBOX_CLIP);

            float pcx = dx * w + cx, pcy = dy * hh + cy;
            float pw = expf(dw) * w, ph = expf(dh) * hh;

            float bx1 = fminf(fmaxf(pcx - 0.5f * pw, 0.0f), IMGF);
            float by1 = fminf(fmaxf(pcy - 0.5f * ph, 0.0f), IMGF);
            float bx2 = fminf(fmaxf(pcx + 0.5f * pw, 0.0f), IMGF);
            float by2 = fminf(fmaxf(pcy + 0.5f * ph, 0.0f), IMGF);

            float* ob = out + ((size_t)img * DETS + rank) * 4;
            ob[0] = bx1 / IMGF;
            ob[1] = by1 / IMGF;
            ob[2] = bx2 / IMGF;
            ob[3] = by2 / IMGF;
            g_keptp[img * DETS + rank] = p;
        }
    }
#if defined(__CUDA_ARCH__) && __CUDA_ARCH__ >= 900
    cudaTriggerProgrammaticLaunchCompletion();
#endif
}

// ---------------------------------------------------------------------------
// K3: feature gather, WIDE (one block per detection), PDL-synced on select.
// ---------------------------------------------------------------------------
__global__ void gather_k(const float* __restrict__ feats, float* __restrict__ out) {
#if defined(__CUDA_ARCH__) && __CUDA_ARCH__ >= 900
    cudaGridDependencySynchronize();           // kept indices now visible
#endif
    int img = blockIdx.x / DETS;
    int p = g_keptp[blockIdx.x];
    const float4* src = (const float4*)(feats + ((size_t)img * PP + p) * FD);
    float4* dst = (float4*)(out + BB * DETS * 4 + (size_t)blockIdx.x * FD);
    dst[threadIdx.x] = src[threadIdx.x];
}

extern "C" void kernel_launch(void* const* d_in, const int* in_sizes, int n_in,
                              void* d_out, int out_size) {
    const float* logits = (const float*)d_in[0];
    const float* reg    = (const float*)d_in[1];
    const float* props  = (const float*)d_in[2];
    const float* feats  = (const float*)d_in[3];
    float* out = (float*)d_out;

    rowmax_k<<<BB * PP / RT, 256>>>(logits);

    cudaLaunchAttribute attr[1];
    attr[0].id = cudaLaunchAttributeProgrammaticStreamSerialization;
    attr[0].val.programmaticStreamSerializationAllowed = 1;

    {
        cudaLaunchConfig_t cfg = {};
        cfg.gridDim = dim3(BB, 1, 1);
        cfg.blockDim = dim3(1024, 1, 1);
        cfg.dynamicSmemBytes = 0;
        cfg.stream = 0;
        cfg.attrs = attr;
        cfg.numAttrs = 1;
        cudaLaunchKernelEx(&cfg, select_k, logits, reg, props, out);
    }
    {
        cudaLaunchConfig_t cfg = {};
        cfg.gridDim = dim3(BB * DETS, 1, 1);
        cfg.blockDim = dim3(256, 1, 1);
        cfg.dynamicSmemBytes = 0;
        cfg.stream = 0;
        cfg.attrs = attr;
        cfg.numAttrs = 1;
        cudaLaunchKernelEx(&cfg, gather_k, feats, out);
    }
}